// round 5
// baseline (speedup 1.0000x reference)
#include <cuda_runtime.h>
#include <cuda_bf16.h>

#define MAXN 50000
#define MAXE 800000
#define MAXG 2500

typedef unsigned long long u64;

// ---- device scratch (no allocations allowed) ----
__device__ __align__(16) float g_h0[MAXN * 16];   // padded concat(x,pos)
__device__ __align__(16) float g_z1[MAXN * 16];   // h0 + agg1 (gather result)
__device__ __align__(16) float g_h1[MAXN * 64];   // conv1 output
__device__ __align__(16) float g_z2[MAXN * 64];   // h1 + agg2 (gather result)
__device__ __align__(16) float g_psum[MAXG * 64]; // pooled sums
__device__ float g_pcnt[MAXG];
__device__ int2  g_edge[MAXE];
__device__ int   g_batch[MAXN];
__device__ int   g_is64;
// CSR by destination
__device__ int g_deg[MAXN];
__device__ int g_off[MAXN + 1];
__device__ int g_cur[MAXN];
__device__ int g_csr[MAXE];       // src node per slot

__device__ __forceinline__ void red_add_v4(float4* addr, float4 v) {
    asm volatile("red.global.add.v4.f32 [%0], {%1,%2,%3,%4};"
                 :: "l"(addr), "f"(v.x), "f"(v.y), "f"(v.z), "f"(v.w)
                 : "memory");
}
__device__ __forceinline__ u64 dup2(float a) {
    u64 r; asm("mov.b64 %0, {%1, %1};" : "=l"(r) : "r"(__float_as_uint(a)));
    return r;
}
__device__ __forceinline__ void ffma2(u64& d, u64 a, u64 b) {
    asm("fma.rn.f32x2 %0, %1, %2, %0;" : "+l"(d) : "l"(a), "l"(b));
}
__device__ __forceinline__ float2 unpack2(u64 v) {
    unsigned lo, hi; asm("mov.b64 {%0, %1}, %2;" : "=r"(lo), "=r"(hi) : "l"(v));
    return make_float2(__uint_as_float(lo), __uint_as_float(hi));
}

// ---- dtype detection: int64 index buffers have all-zero high words ----
__global__ void detect_kernel(const unsigned int* __restrict__ ei_raw, int E) {
    if (blockIdx.x == 0 && threadIdx.x == 0) {
        int is64 = 1;
        for (int s = 0; s < 1024; s++) {
            long i = (long)s * E / 1024;
            if (ei_raw[2 * i + 1] != 0u) { is64 = 0; break; }
        }
        g_is64 = is64;
    }
}

// ---- init: padded h0, edges+batch -> int32, zero deg/psum/pcnt ----
__global__ void init_kernel(const float* __restrict__ x, const float* __restrict__ pos,
                            const void* __restrict__ ei, const void* __restrict__ batch,
                            int n, int E, int G) {
    int i = blockIdx.x * blockDim.x + threadIdx.x;
    int is64 = g_is64;
    if (i < n * 16) {
        int node = i >> 4, c = i & 15;
        float v = 0.f;
        if (c < 11)       v = x[node * 11 + c];
        else if (c < 14)  v = pos[node * 3 + (c - 11)];
        g_h0[i] = v;
    }
    if (i < E) {
        int s, d;
        if (is64) {
            const long long* p = (const long long*)ei;
            s = (int)p[i]; d = (int)p[E + i];
        } else {
            const int* p = (const int*)ei;
            s = p[i]; d = p[E + i];
        }
        g_edge[i] = make_int2(s, d);
    }
    if (i < n) {
        g_batch[i] = is64 ? (int)((const long long*)batch)[i]
                          : ((const int*)batch)[i];
        g_deg[i] = 0;
    }
    if (i < G * 64) g_psum[i] = 0.f;
    if (i < G)      g_pcnt[i] = 0.f;
}

// ---- degree histogram + graph node counts ----
__global__ void count_kernel(int n, int E) {
    int i = blockIdx.x * blockDim.x + threadIdx.x;
    if (i < E) atomicAdd(&g_deg[g_edge[i].y], 1);
    if (i < n) atomicAdd(&g_pcnt[g_batch[i]], 1.f);
}

// ---- single-block exclusive scan over degrees -> offsets + cursors ----
__global__ void scan_kernel(int n) {
    __shared__ int ssum[1024];
    int tid = threadIdx.x;
    int chunk = (n + 1023) >> 10;
    int lo = tid * chunk, hi = min(lo + chunk, n);
    int s = 0;
    for (int i = lo; i < hi; i++) s += g_deg[i];
    ssum[tid] = s;
    __syncthreads();
    // inclusive Hillis-Steele scan over 1024 partials
    #pragma unroll
    for (int off = 1; off < 1024; off <<= 1) {
        int v = (tid >= off) ? ssum[tid - off] : 0;
        __syncthreads();
        ssum[tid] += v;
        __syncthreads();
    }
    int run = ssum[tid] - s;   // exclusive prefix for this chunk
    for (int i = lo; i < hi; i++) {
        g_off[i] = run;
        g_cur[i] = run;
        run += g_deg[i];
    }
    if (hi == n && lo <= n) g_off[n] = run;
}

// ---- CSR fill: slot per (dst) via atomic cursor ----
__global__ void fill_kernel(int E) {
    int i = blockIdx.x * blockDim.x + threadIdx.x;
    if (i >= E) return;
    int2 ed = g_edge[i];
    int slot = atomicAdd(&g_cur[ed.y], 1);
    g_csr[slot] = ed.x;
}

// ---- gather-aggregate: z[node] = h[node] + sum_{j in N(node)} h[j] ----
// LANES lanes cooperate per node, each owning one float4 column.
template<int LANES, bool FIRST>
__global__ void agg_kernel(int n) {
    int gi = blockIdx.x * blockDim.x + threadIdx.x;
    int node = gi / LANES;
    int lane = gi % LANES;
    if (node >= n) return;
    const float4* __restrict__ h = FIRST ? (const float4*)g_h0 : (const float4*)g_h1;
    float4* z = FIRST ? (float4*)g_z1 : (float4*)g_z2;
    float4 acc = h[(size_t)node * LANES + lane];   // self term
    int lo = g_off[node], hi = g_off[node + 1];
    #pragma unroll 4
    for (int j = lo; j < hi; j++) {
        int s = g_csr[j];
        float4 v = h[(size_t)s * LANES + lane];
        acc.x += v.x; acc.y += v.y; acc.z += v.z; acc.w += v.w;
    }
    z[(size_t)node * LANES + lane] = acc;
}

// ---- fused GIN MLP with packed f32x2, 2-tile register-lean layout ----
// PHASE 1: z = g_z1 [n,16] -> writes g_h1
// PHASE 2: z = g_z2 [n,64] -> relu + red-add into g_psum[batch[node]]
template<int DIN, int PHASE>
__launch_bounds__(128, 4)
__global__ void mlp_kernel(const float* __restrict__ Wa, const float* __restrict__ ba,
                           const float* __restrict__ Wb, const float* __restrict__ bb,
                           int wa_rows, int n) {
    __shared__ __align__(16) float sWa[DIN * 64];
    __shared__ __align__(16) float sWb[64 * 64];
    __shared__ __align__(16) float sb[128];      // ba | bb

    int tid = threadIdx.x;
    for (int i = tid; i < DIN * 64; i += 128) sWa[i] = (i < wa_rows * 64) ? Wa[i] : 0.f;
    for (int i = tid; i < 64 * 64; i += 128)  sWb[i] = Wb[i];
    if (tid < 64) sb[tid] = ba[tid]; else sb[tid] = bb[tid - 64];
    __syncthreads();

    int node = blockIdx.x * 128 + tid;
    if (node >= n) return;

    const float4* __restrict__ zr4 = (const float4*)
        (((PHASE == 1) ? g_z1 : g_z2) + (size_t)node * DIN);
    const u64* sbp = (const u64*)sb;

    float t[64];

    // ---- GEMM1: two tiles of 32 outputs (16 packed pairs each) ----
    #pragma unroll
    for (int jt = 0; jt < 2; jt++) {
        u64 acc[16];
        #pragma unroll
        for (int j = 0; j < 16; j++) acc[j] = sbp[jt * 16 + j];
        #pragma unroll
        for (int k4 = 0; k4 < DIN / 4; k4++) {
            float4 zv = zr4[k4];
            #pragma unroll
            for (int kk = 0; kk < 4; kk++) {
                u64 zk2 = dup2((&zv.x)[kk]);
                const u64* w = (const u64*)&sWa[(k4 * 4 + kk) * 64 + jt * 32];
                #pragma unroll
                for (int j = 0; j < 16; j++) ffma2(acc[j], zk2, w[j]);
            }
        }
        #pragma unroll
        for (int j = 0; j < 16; j++) {
            float2 p = unpack2(acc[j]);
            t[jt * 32 + 2 * j]     = fmaxf(p.x, 0.f);
            t[jt * 32 + 2 * j + 1] = fmaxf(p.y, 0.f);
        }
    }

    // ---- GEMM2: two tiles of 32 outputs ----
    #pragma unroll
    for (int jt = 0; jt < 2; jt++) {
        u64 acc[16];
        #pragma unroll
        for (int j = 0; j < 16; j++) acc[j] = sbp[32 + jt * 16 + j];
        #pragma unroll
        for (int k = 0; k < 64; k++) {
            u64 tk2 = dup2(t[k]);
            const u64* w = (const u64*)&sWb[k * 64 + jt * 32];
            #pragma unroll
            for (int j = 0; j < 16; j++) ffma2(acc[j], tk2, w[j]);
        }
        if (PHASE == 1) {
            float4* o1 = (float4*)&g_h1[(size_t)node * 64 + jt * 32];
            #pragma unroll
            for (int j = 0; j < 8; j++) {
                float2 p0 = unpack2(acc[2 * j]);
                float2 p1 = unpack2(acc[2 * j + 1]);
                o1[j] = make_float4(fmaxf(p0.x, 0.f), fmaxf(p0.y, 0.f),
                                    fmaxf(p1.x, 0.f), fmaxf(p1.y, 0.f));
            }
        } else {
            int g = g_batch[node];
            float4* ps = (float4*)&g_psum[(size_t)g * 64 + jt * 32];
            #pragma unroll
            for (int j = 0; j < 8; j++) {
                float2 p0 = unpack2(acc[2 * j]);
                float2 p1 = unpack2(acc[2 * j + 1]);
                red_add_v4(&ps[j], make_float4(fmaxf(p0.x, 0.f), fmaxf(p0.y, 0.f),
                                               fmaxf(p1.x, 0.f), fmaxf(p1.y, 0.f)));
            }
        }
    }
}

// ---- final: out[g] = dot(psum[g], Wlin) / max(cnt,1) + blin ----
__global__ void final_kernel(const float* __restrict__ Wlin, const float* __restrict__ blin,
                             float* __restrict__ out, int G) {
    int gw = (blockIdx.x * blockDim.x + threadIdx.x) >> 5;
    int lane = threadIdx.x & 31;
    if (gw >= G) return;
    float s = g_psum[gw * 64 + lane] * Wlin[lane]
            + g_psum[gw * 64 + 32 + lane] * Wlin[32 + lane];
    #pragma unroll
    for (int o = 16; o; o >>= 1) s += __shfl_down_sync(0xffffffffu, s, o);
    if (lane == 0) out[gw] = s / fmaxf(g_pcnt[gw], 1.f) + blin[0];
}

extern "C" void kernel_launch(void* const* d_in, const int* in_sizes, int n_in,
                              void* d_out, int out_size) {
    const float* x     = (const float*)d_in[0];
    const float* pos   = (const float*)d_in[1];
    const void*  eidx  = d_in[2];
    const void*  batch = d_in[3];
    const float* W1a = (const float*)d_in[4];
    const float* b1a = (const float*)d_in[5];
    const float* W1b = (const float*)d_in[6];
    const float* b1b = (const float*)d_in[7];
    const float* W2a = (const float*)d_in[8];
    const float* b2a = (const float*)d_in[9];
    const float* W2b = (const float*)d_in[10];
    const float* b2b = (const float*)d_in[11];
    const float* Wlin = (const float*)d_in[12];
    const float* blin = (const float*)d_in[13];
    float* out = (float*)d_out;

    int n = in_sizes[3];
    int E = in_sizes[2] / 2;
    int G = out_size;

    detect_kernel<<<1, 32>>>((const unsigned int*)eidx, E);

    int initN = n * 16 > E ? n * 16 : E;
    if (G * 64 > initN) initN = G * 64;
    init_kernel<<<(initN + 255) / 256, 256>>>(x, pos, eidx, batch, n, E, G);

    int cntN = E > n ? E : n;
    count_kernel<<<(cntN + 255) / 256, 256>>>(n, E);
    scan_kernel<<<1, 1024>>>(n);
    fill_kernel<<<(E + 255) / 256, 256>>>(E);

    // conv1 aggregation: z1 = h0 + gathered neighbor sum (4 lanes/node)
    agg_kernel<4, true><<<(n * 4 + 255) / 256, 256>>>(n);

    // conv1 MLP: z1[n,16] -> h1
    mlp_kernel<16, 1><<<(n + 127) / 128, 128>>>(W1a, b1a, W1b, b1b, 14, n);

    // conv2 aggregation: z2 = h1 + gathered neighbor sum (16 lanes/node)
    agg_kernel<16, false><<<(n * 16 + 255) / 256, 256>>>(n);

    // conv2 MLP: z2[n,64] -> relu -> pooled sums (fused)
    mlp_kernel<64, 2><<<(n + 127) / 128, 128>>>(W2a, b2a, W2b, b2b, 64, n);

    final_kernel<<<(G * 32 + 255) / 256, 256>>>(Wlin, blin, out, G);
}

// round 6
// speedup vs baseline: 1.5983x; 1.5983x over previous
#include <cuda_runtime.h>
#include <cuda_bf16.h>

#define MAXN 50000
#define MAXE 800000
#define MAXG 2500
#define MAXB ((MAXN + 255) / 256)

typedef unsigned long long u64;

// ---- device scratch (no allocations allowed) ----
__device__ __align__(16) float g_h0[MAXN * 16];   // padded concat(x,pos)
__device__ __align__(16) float g_z1[MAXN * 16];   // h0 + agg1 (gather result)
__device__ __align__(16) float g_h1[MAXN * 64];   // conv1 output
__device__ __align__(16) float g_z2[MAXN * 64];   // h1 + agg2 (gather result)
__device__ __align__(16) float g_psum[MAXG * 64]; // pooled sums
__device__ float g_pcnt[MAXG];
__device__ int2  g_edge[MAXE];
__device__ int   g_batch[MAXN];
__device__ int   g_is64;
// CSR by destination
__device__ int g_deg[MAXN];
__device__ int g_off[MAXN + 1];
__device__ int g_cur[MAXN];
__device__ int g_csr[MAXE];       // src node per slot
__device__ int g_bsum[MAXB];
__device__ int g_boff[MAXB];

__device__ __forceinline__ void red_add_v4(float4* addr, float4 v) {
    asm volatile("red.global.add.v4.f32 [%0], {%1,%2,%3,%4};"
                 :: "l"(addr), "f"(v.x), "f"(v.y), "f"(v.z), "f"(v.w)
                 : "memory");
}
__device__ __forceinline__ u64 dup2(float a) {
    u64 r; asm("mov.b64 %0, {%1, %1};" : "=l"(r) : "r"(__float_as_uint(a)));
    return r;
}
__device__ __forceinline__ void ffma2(u64& d, u64 a, u64 b) {
    asm("fma.rn.f32x2 %0, %1, %2, %0;" : "+l"(d) : "l"(a), "l"(b));
}
__device__ __forceinline__ float2 unpack2(u64 v) {
    unsigned lo, hi; asm("mov.b64 {%0, %1}, %2;" : "=r"(lo), "=r"(hi) : "l"(v));
    return make_float2(__uint_as_float(lo), __uint_as_float(hi));
}

// ---- dtype detection: int64 index buffers have all-zero high words ----
__global__ void detect_kernel(const unsigned int* __restrict__ ei_raw, int E) {
    if (blockIdx.x == 0 && threadIdx.x == 0) {
        int is64 = 1;
        for (int s = 0; s < 1024; s++) {
            long i = (long)s * E / 1024;
            if (ei_raw[2 * i + 1] != 0u) { is64 = 0; break; }
        }
        g_is64 = is64;
    }
}

// ---- init: padded h0, edges+batch -> int32, zero deg/psum/pcnt ----
__global__ void init_kernel(const float* __restrict__ x, const float* __restrict__ pos,
                            const void* __restrict__ ei, const void* __restrict__ batch,
                            int n, int E, int G) {
    int i = blockIdx.x * blockDim.x + threadIdx.x;
    int is64 = g_is64;
    if (i < n * 16) {
        int node = i >> 4, c = i & 15;
        float v = 0.f;
        if (c < 11)       v = x[node * 11 + c];
        else if (c < 14)  v = pos[node * 3 + (c - 11)];
        g_h0[i] = v;
    }
    if (i < E) {
        int s, d;
        if (is64) {
            const long long* p = (const long long*)ei;
            s = (int)p[i]; d = (int)p[E + i];
        } else {
            const int* p = (const int*)ei;
            s = p[i]; d = p[E + i];
        }
        g_edge[i] = make_int2(s, d);
    }
    if (i < n) {
        g_batch[i] = is64 ? (int)((const long long*)batch)[i]
                          : ((const int*)batch)[i];
        g_deg[i] = 0;
    }
    if (i < G * 64) g_psum[i] = 0.f;
    if (i < G)      g_pcnt[i] = 0.f;
}

// ---- degree histogram + graph node counts ----
__global__ void count_kernel(int n, int E) {
    int i = blockIdx.x * blockDim.x + threadIdx.x;
    if (i < E) atomicAdd(&g_deg[g_edge[i].y], 1);
    if (i < n) atomicAdd(&g_pcnt[g_batch[i]], 1.f);
}

// ---- 3-phase parallel exclusive scan over degrees ----
__global__ void scan1(int n) {
    __shared__ int s[256];
    int tid = threadIdx.x;
    int i = blockIdx.x * 256 + tid;
    int v = (i < n) ? g_deg[i] : 0;
    s[tid] = v;
    __syncthreads();
    #pragma unroll
    for (int off = 1; off < 256; off <<= 1) {
        int t = (tid >= off) ? s[tid - off] : 0;
        __syncthreads();
        s[tid] += t;
        __syncthreads();
    }
    if (i < n) g_off[i] = s[tid] - v;          // block-local exclusive
    if (tid == 255) g_bsum[blockIdx.x] = s[255];
}

__global__ void scan2(int B, int n) {
    __shared__ int s[1024];
    int tid = threadIdx.x;
    int v = (tid < B) ? g_bsum[tid] : 0;
    s[tid] = v;
    __syncthreads();
    #pragma unroll
    for (int off = 1; off < 1024; off <<= 1) {
        int t = (tid >= off) ? s[tid - off] : 0;
        __syncthreads();
        s[tid] += t;
        __syncthreads();
    }
    if (tid < B) g_boff[tid] = s[tid] - v;     // exclusive block offsets
    if (tid == B - 1) g_off[n] = s[tid];       // total
}

__global__ void scan3(int n) {
    int i = blockIdx.x * blockDim.x + threadIdx.x;
    if (i < n) {
        int o = g_off[i] + g_boff[i >> 8];
        g_off[i] = o;
        g_cur[i] = o;
    }
}

// ---- CSR fill: slot per dst via atomic cursor ----
__global__ void fill_kernel(int E) {
    int i = blockIdx.x * blockDim.x + threadIdx.x;
    if (i >= E) return;
    int2 ed = g_edge[i];
    int slot = atomicAdd(&g_cur[ed.y], 1);
    g_csr[slot] = ed.x;
}

// ---- gather-aggregate: z[node] = h[node] + sum_{j in N(node)} h[j] ----
template<int LANES, bool FIRST>
__global__ void agg_kernel(int n) {
    int gi = blockIdx.x * blockDim.x + threadIdx.x;
    int node = gi / LANES;
    int lane = gi % LANES;
    if (node >= n) return;
    const float4* __restrict__ h = FIRST ? (const float4*)g_h0 : (const float4*)g_h1;
    float4* z = FIRST ? (float4*)g_z1 : (float4*)g_z2;
    float4 acc = h[(size_t)node * LANES + lane];   // self term
    int lo = g_off[node], hi = g_off[node + 1];
    #pragma unroll 4
    for (int j = lo; j < hi; j++) {
        int s = g_csr[j];
        float4 v = h[(size_t)s * LANES + lane];
        acc.x += v.x; acc.y += v.y; acc.z += v.z; acc.w += v.w;
    }
    z[(size_t)node * LANES + lane] = acc;
}

// ---- fused GIN MLP with packed f32x2, 2-tile register-lean layout ----
// PHASE 1: z = g_z1 [n,16] -> writes g_h1
// PHASE 2: z = g_z2 [n,64] -> relu + red-add into g_psum[batch[node]]
template<int DIN, int PHASE>
__launch_bounds__(128, 4)
__global__ void mlp_kernel(const float* __restrict__ Wa, const float* __restrict__ ba,
                           const float* __restrict__ Wb, const float* __restrict__ bb,
                           int wa_rows, int n) {
    __shared__ __align__(16) float sWa[DIN * 64];
    __shared__ __align__(16) float sWb[64 * 64];
    __shared__ __align__(16) float sb[128];      // ba | bb

    int tid = threadIdx.x;
    for (int i = tid; i < DIN * 64; i += 128) sWa[i] = (i < wa_rows * 64) ? Wa[i] : 0.f;
    for (int i = tid; i < 64 * 64; i += 128)  sWb[i] = Wb[i];
    if (tid < 64) sb[tid] = ba[tid]; else sb[tid] = bb[tid - 64];
    __syncthreads();

    int node = blockIdx.x * 128 + tid;
    if (node >= n) return;

    const float4* __restrict__ zr4 = (const float4*)
        (((PHASE == 1) ? g_z1 : g_z2) + (size_t)node * DIN);
    const u64* sbp = (const u64*)sb;

    float t[64];

    // ---- GEMM1: two tiles of 32 outputs (16 packed pairs each) ----
    #pragma unroll
    for (int jt = 0; jt < 2; jt++) {
        u64 acc[16];
        #pragma unroll
        for (int j = 0; j < 16; j++) acc[j] = sbp[jt * 16 + j];
        #pragma unroll
        for (int k4 = 0; k4 < DIN / 4; k4++) {
            float4 zv = zr4[k4];
            #pragma unroll
            for (int kk = 0; kk < 4; kk++) {
                u64 zk2 = dup2((&zv.x)[kk]);
                const u64* w = (const u64*)&sWa[(k4 * 4 + kk) * 64 + jt * 32];
                #pragma unroll
                for (int j = 0; j < 16; j++) ffma2(acc[j], zk2, w[j]);
            }
        }
        #pragma unroll
        for (int j = 0; j < 16; j++) {
            float2 p = unpack2(acc[j]);
            t[jt * 32 + 2 * j]     = fmaxf(p.x, 0.f);
            t[jt * 32 + 2 * j + 1] = fmaxf(p.y, 0.f);
        }
    }

    // ---- GEMM2: two tiles of 32 outputs ----
    #pragma unroll
    for (int jt = 0; jt < 2; jt++) {
        u64 acc[16];
        #pragma unroll
        for (int j = 0; j < 16; j++) acc[j] = sbp[32 + jt * 16 + j];
        #pragma unroll
        for (int k = 0; k < 64; k++) {
            u64 tk2 = dup2(t[k]);
            const u64* w = (const u64*)&sWb[k * 64 + jt * 32];
            #pragma unroll
            for (int j = 0; j < 16; j++) ffma2(acc[j], tk2, w[j]);
        }
        if (PHASE == 1) {
            float4* o1 = (float4*)&g_h1[(size_t)node * 64 + jt * 32];
            #pragma unroll
            for (int j = 0; j < 8; j++) {
                float2 p0 = unpack2(acc[2 * j]);
                float2 p1 = unpack2(acc[2 * j + 1]);
                o1[j] = make_float4(fmaxf(p0.x, 0.f), fmaxf(p0.y, 0.f),
                                    fmaxf(p1.x, 0.f), fmaxf(p1.y, 0.f));
            }
        } else {
            int g = g_batch[node];
            float4* ps = (float4*)&g_psum[(size_t)g * 64 + jt * 32];
            #pragma unroll
            for (int j = 0; j < 8; j++) {
                float2 p0 = unpack2(acc[2 * j]);
                float2 p1 = unpack2(acc[2 * j + 1]);
                red_add_v4(&ps[j], make_float4(fmaxf(p0.x, 0.f), fmaxf(p0.y, 0.f),
                                               fmaxf(p1.x, 0.f), fmaxf(p1.y, 0.f)));
            }
        }
    }
}

// ---- final: out[g] = dot(psum[g], Wlin) / max(cnt,1) + blin ----
__global__ void final_kernel(const float* __restrict__ Wlin, const float* __restrict__ blin,
                             float* __restrict__ out, int G) {
    int gw = (blockIdx.x * blockDim.x + threadIdx.x) >> 5;
    int lane = threadIdx.x & 31;
    if (gw >= G) return;
    float s = g_psum[gw * 64 + lane] * Wlin[lane]
            + g_psum[gw * 64 + 32 + lane] * Wlin[32 + lane];
    #pragma unroll
    for (int o = 16; o; o >>= 1) s += __shfl_down_sync(0xffffffffu, s, o);
    if (lane == 0) out[gw] = s / fmaxf(g_pcnt[gw], 1.f) + blin[0];
}

extern "C" void kernel_launch(void* const* d_in, const int* in_sizes, int n_in,
                              void* d_out, int out_size) {
    const float* x     = (const float*)d_in[0];
    const float* pos   = (const float*)d_in[1];
    const void*  eidx  = d_in[2];
    const void*  batch = d_in[3];
    const float* W1a = (const float*)d_in[4];
    const float* b1a = (const float*)d_in[5];
    const float* W1b = (const float*)d_in[6];
    const float* b1b = (const float*)d_in[7];
    const float* W2a = (const float*)d_in[8];
    const float* b2a = (const float*)d_in[9];
    const float* W2b = (const float*)d_in[10];
    const float* b2b = (const float*)d_in[11];
    const float* Wlin = (const float*)d_in[12];
    const float* blin = (const float*)d_in[13];
    float* out = (float*)d_out;

    int n = in_sizes[3];
    int E = in_sizes[2] / 2;
    int G = out_size;

    detect_kernel<<<1, 32>>>((const unsigned int*)eidx, E);

    int initN = n * 16 > E ? n * 16 : E;
    if (G * 64 > initN) initN = G * 64;
    init_kernel<<<(initN + 255) / 256, 256>>>(x, pos, eidx, batch, n, E, G);

    int cntN = E > n ? E : n;
    count_kernel<<<(cntN + 255) / 256, 256>>>(n, E);

    int B = (n + 255) / 256;
    scan1<<<B, 256>>>(n);
    scan2<<<1, 1024>>>(B, n);
    scan3<<<(n + 255) / 256, 256>>>(n);
    fill_kernel<<<(E + 255) / 256, 256>>>(E);

    // conv1 aggregation: z1 = h0 + gathered neighbor sum (4 lanes/node)
    agg_kernel<4, true><<<(n * 4 + 255) / 256, 256>>>(n);

    // conv1 MLP: z1[n,16] -> h1
    mlp_kernel<16, 1><<<(n + 127) / 128, 128>>>(W1a, b1a, W1b, b1b, 14, n);

    // conv2 aggregation: z2 = h1 + gathered neighbor sum (16 lanes/node)
    agg_kernel<16, false><<<(n * 16 + 255) / 256, 256>>>(n);

    // conv2 MLP: z2[n,64] -> relu -> pooled sums (fused)
    mlp_kernel<64, 2><<<(n + 127) / 128, 128>>>(W2a, b2a, W2b, b2b, 64, n);

    final_kernel<<<(G * 32 + 255) / 256, 256>>>(Wlin, blin, out, G);
}

// round 7
// speedup vs baseline: 1.6378x; 1.0247x over previous
#include <cuda_runtime.h>
#include <cuda_bf16.h>

#define MAXN 50000
#define MAXE 800000
#define MAXG 2500
#define MAXB ((MAXN + 255) / 256)

typedef unsigned long long u64;

// ---- device scratch (no allocations allowed) ----
__device__ __align__(16) float g_h0[MAXN * 16];   // padded concat(x,pos)
__device__ __align__(16) float g_z1[MAXN * 16];   // h0 + agg1 (gather result)
__device__ __align__(16) float g_h1[MAXN * 64];   // conv1 output
__device__ __align__(16) float g_z2[MAXN * 64];   // h1 + agg2 (gather result)
__device__ __align__(16) float g_psum[MAXG * 64]; // pooled sums
__device__ float g_pcnt[MAXG];
__device__ int2  g_edge[MAXE];
__device__ int   g_batch[MAXN];
__device__ int   g_is64;
// CSR by destination
__device__ int g_deg[MAXN];
__device__ int g_off[MAXN + 1];
__device__ int g_cur[MAXN];
__device__ int g_csr[MAXE];       // src node per slot
__device__ int g_bsum[MAXB];
__device__ int g_boff[MAXB];

__device__ __forceinline__ void red_add_v4(float4* addr, float4 v) {
    asm volatile("red.global.add.v4.f32 [%0], {%1,%2,%3,%4};"
                 :: "l"(addr), "f"(v.x), "f"(v.y), "f"(v.z), "f"(v.w)
                 : "memory");
}
__device__ __forceinline__ u64 dup2(float a) {
    u64 r; asm("mov.b64 %0, {%1, %1};" : "=l"(r) : "r"(__float_as_uint(a)));
    return r;
}
__device__ __forceinline__ void ffma2(u64& d, u64 a, u64 b) {
    asm("fma.rn.f32x2 %0, %1, %2, %0;" : "+l"(d) : "l"(a), "l"(b));
}
__device__ __forceinline__ float2 unpack2(u64 v) {
    unsigned lo, hi; asm("mov.b64 {%0, %1}, %2;" : "=r"(lo), "=r"(hi) : "l"(v));
    return make_float2(__uint_as_float(lo), __uint_as_float(hi));
}

// ---- dtype detection: int64 index buffers have all-zero high words ----
__global__ void detect_kernel(const unsigned int* __restrict__ ei_raw, int E) {
    if (blockIdx.x == 0 && threadIdx.x == 0) {
        int is64 = 1;
        for (int s = 0; s < 1024; s++) {
            long i = (long)s * E / 1024;
            if (ei_raw[2 * i + 1] != 0u) { is64 = 0; break; }
        }
        g_is64 = is64;
    }
}

// ---- zero counters before init's fused atomics ----
__global__ void zero_kernel(int n, int G) {
    int i = blockIdx.x * blockDim.x + threadIdx.x;
    if (i < n)      g_deg[i] = 0;
    if (i < G * 64) g_psum[i] = 0.f;
    if (i < G)      g_pcnt[i] = 0.f;
}

// ---- init: padded h0, edges+batch -> int32, fused degree & pcnt histograms ----
__global__ void init_kernel(const float* __restrict__ x, const float* __restrict__ pos,
                            const void* __restrict__ ei, const void* __restrict__ batch,
                            int n, int E) {
    int i = blockIdx.x * blockDim.x + threadIdx.x;
    int is64 = g_is64;
    if (i < n * 16) {
        int node = i >> 4, c = i & 15;
        float v = 0.f;
        if (c < 11)       v = x[node * 11 + c];
        else if (c < 14)  v = pos[node * 3 + (c - 11)];
        g_h0[i] = v;
    }
    if (i < E) {
        int s, d;
        if (is64) {
            const long long* p = (const long long*)ei;
            s = (int)p[i]; d = (int)p[E + i];
        } else {
            const int* p = (const int*)ei;
            s = p[i]; d = p[E + i];
        }
        g_edge[i] = make_int2(s, d);
        atomicAdd(&g_deg[d], 1);
    }
    if (i < n) {
        int b = is64 ? (int)((const long long*)batch)[i]
                     : ((const int*)batch)[i];
        g_batch[i] = b;
        atomicAdd(&g_pcnt[b], 1.f);
    }
}

// ---- 3-phase parallel exclusive scan over degrees ----
__global__ void scan1(int n) {
    __shared__ int s[256];
    int tid = threadIdx.x;
    int i = blockIdx.x * 256 + tid;
    int v = (i < n) ? g_deg[i] : 0;
    s[tid] = v;
    __syncthreads();
    #pragma unroll
    for (int off = 1; off < 256; off <<= 1) {
        int t = (tid >= off) ? s[tid - off] : 0;
        __syncthreads();
        s[tid] += t;
        __syncthreads();
    }
    if (i < n) g_off[i] = s[tid] - v;          // block-local exclusive
    if (tid == 255) g_bsum[blockIdx.x] = s[255];
}

__global__ void scan2(int B, int n) {
    __shared__ int s[1024];
    int tid = threadIdx.x;
    int v = (tid < B) ? g_bsum[tid] : 0;
    s[tid] = v;
    __syncthreads();
    #pragma unroll
    for (int off = 1; off < 1024; off <<= 1) {
        int t = (tid >= off) ? s[tid - off] : 0;
        __syncthreads();
        s[tid] += t;
        __syncthreads();
    }
    if (tid < B) g_boff[tid] = s[tid] - v;     // exclusive block offsets
    if (tid == B - 1) g_off[n] = s[tid];       // total
}

__global__ void scan3(int n) {
    int i = blockIdx.x * blockDim.x + threadIdx.x;
    if (i < n) {
        int o = g_off[i] + g_boff[i >> 8];
        g_off[i] = o;
        g_cur[i] = o;
    }
}

// ---- CSR fill: slot per dst via atomic cursor ----
__global__ void fill_kernel(int E) {
    int i = blockIdx.x * blockDim.x + threadIdx.x;
    if (i >= E) return;
    int2 ed = g_edge[i];
    int slot = atomicAdd(&g_cur[ed.y], 1);
    g_csr[slot] = ed.x;
}

// ---- gather-aggregate: z[node] = h[node] + sum_{j in N(node)} h[j] ----
template<int LANES, bool FIRST>
__global__ void agg_kernel(int n) {
    int gi = blockIdx.x * blockDim.x + threadIdx.x;
    int node = gi / LANES;
    int lane = gi % LANES;
    if (node >= n) return;
    const float4* __restrict__ h = FIRST ? (const float4*)g_h0 : (const float4*)g_h1;
    float4* z = FIRST ? (float4*)g_z1 : (float4*)g_z2;
    float4 acc = h[(size_t)node * LANES + lane];   // self term
    int lo = g_off[node], hi = g_off[node + 1];
    #pragma unroll 4
    for (int j = lo; j < hi; j++) {
        int s = g_csr[j];
        float4 v = h[(size_t)s * LANES + lane];
        acc.x += v.x; acc.y += v.y; acc.z += v.z; acc.w += v.w;
    }
    z[(size_t)node * LANES + lane] = acc;
}

// ---- fused GIN MLP: packed f32x2 math, LDS.128 weight loads ----
// PHASE 1: z = g_z1 [n,16] -> writes g_h1
// PHASE 2: z = g_z2 [n,64] -> relu + red-add into g_psum[batch[node]]
template<int DIN, int PHASE>
__launch_bounds__(128, 4)
__global__ void mlp_kernel(const float* __restrict__ Wa, const float* __restrict__ ba,
                           const float* __restrict__ Wb, const float* __restrict__ bb,
                           int wa_rows, int n) {
    __shared__ __align__(16) float sWa[DIN * 64];
    __shared__ __align__(16) float sWb[64 * 64];
    __shared__ __align__(16) float sb[128];      // ba | bb

    int tid = threadIdx.x;
    for (int i = tid; i < DIN * 64; i += 128) sWa[i] = (i < wa_rows * 64) ? Wa[i] : 0.f;
    for (int i = tid; i < 64 * 64; i += 128)  sWb[i] = Wb[i];
    if (tid < 64) sb[tid] = ba[tid]; else sb[tid] = bb[tid - 64];
    __syncthreads();

    int node = blockIdx.x * 128 + tid;
    if (node >= n) return;

    const float4* __restrict__ zr4 = (const float4*)
        (((PHASE == 1) ? g_z1 : g_z2) + (size_t)node * DIN);
    const u64* sbp = (const u64*)sb;

    float t[64];

    // ---- GEMM1: two tiles of 32 outputs (16 packed pairs each) ----
    #pragma unroll
    for (int jt = 0; jt < 2; jt++) {
        u64 acc[16];
        #pragma unroll
        for (int j = 0; j < 16; j++) acc[j] = sbp[jt * 16 + j];
        #pragma unroll
        for (int k4 = 0; k4 < DIN / 4; k4++) {
            float4 zv = zr4[k4];
            #pragma unroll
            for (int kk = 0; kk < 4; kk++) {
                u64 zk2 = dup2((&zv.x)[kk]);
                const ulonglong2* w = (const ulonglong2*)&sWa[(k4 * 4 + kk) * 64 + jt * 32];
                #pragma unroll
                for (int j = 0; j < 8; j++) {
                    ulonglong2 wv = w[j];
                    ffma2(acc[2 * j],     zk2, wv.x);
                    ffma2(acc[2 * j + 1], zk2, wv.y);
                }
            }
        }
        #pragma unroll
        for (int j = 0; j < 16; j++) {
            float2 p = unpack2(acc[j]);
            t[jt * 32 + 2 * j]     = fmaxf(p.x, 0.f);
            t[jt * 32 + 2 * j + 1] = fmaxf(p.y, 0.f);
        }
    }

    // ---- GEMM2: two tiles of 32 outputs ----
    #pragma unroll
    for (int jt = 0; jt < 2; jt++) {
        u64 acc[16];
        #pragma unroll
        for (int j = 0; j < 16; j++) acc[j] = sbp[32 + jt * 16 + j];
        #pragma unroll
        for (int k = 0; k < 64; k++) {
            u64 tk2 = dup2(t[k]);
            const ulonglong2* w = (const ulonglong2*)&sWb[k * 64 + jt * 32];
            #pragma unroll
            for (int j = 0; j < 8; j++) {
                ulonglong2 wv = w[j];
                ffma2(acc[2 * j],     tk2, wv.x);
                ffma2(acc[2 * j + 1], tk2, wv.y);
            }
        }
        if (PHASE == 1) {
            float4* o1 = (float4*)&g_h1[(size_t)node * 64 + jt * 32];
            #pragma unroll
            for (int j = 0; j < 8; j++) {
                float2 p0 = unpack2(acc[2 * j]);
                float2 p1 = unpack2(acc[2 * j + 1]);
                o1[j] = make_float4(fmaxf(p0.x, 0.f), fmaxf(p0.y, 0.f),
                                    fmaxf(p1.x, 0.f), fmaxf(p1.y, 0.f));
            }
        } else {
            int g = g_batch[node];
            float4* ps = (float4*)&g_psum[(size_t)g * 64 + jt * 32];
            #pragma unroll
            for (int j = 0; j < 8; j++) {
                float2 p0 = unpack2(acc[2 * j]);
                float2 p1 = unpack2(acc[2 * j + 1]);
                red_add_v4(&ps[j], make_float4(fmaxf(p0.x, 0.f), fmaxf(p0.y, 0.f),
                                               fmaxf(p1.x, 0.f), fmaxf(p1.y, 0.f)));
            }
        }
    }
}

// ---- final: out[g] = dot(psum[g], Wlin) / max(cnt,1) + blin ----
__global__ void final_kernel(const float* __restrict__ Wlin, const float* __restrict__ blin,
                             float* __restrict__ out, int G) {
    int gw = (blockIdx.x * blockDim.x + threadIdx.x) >> 5;
    int lane = threadIdx.x & 31;
    if (gw >= G) return;
    float s = g_psum[gw * 64 + lane] * Wlin[lane]
            + g_psum[gw * 64 + 32 + lane] * Wlin[32 + lane];
    #pragma unroll
    for (int o = 16; o; o >>= 1) s += __shfl_down_sync(0xffffffffu, s, o);
    if (lane == 0) out[gw] = s / fmaxf(g_pcnt[gw], 1.f) + blin[0];
}

extern "C" void kernel_launch(void* const* d_in, const int* in_sizes, int n_in,
                              void* d_out, int out_size) {
    const float* x     = (const float*)d_in[0];
    const float* pos   = (const float*)d_in[1];
    const void*  eidx  = d_in[2];
    const void*  batch = d_in[3];
    const float* W1a = (const float*)d_in[4];
    const float* b1a = (const float*)d_in[5];
    const float* W1b = (const float*)d_in[6];
    const float* b1b = (const float*)d_in[7];
    const float* W2a = (const float*)d_in[8];
    const float* b2a = (const float*)d_in[9];
    const float* W2b = (const float*)d_in[10];
    const float* b2b = (const float*)d_in[11];
    const float* Wlin = (const float*)d_in[12];
    const float* blin = (const float*)d_in[13];
    float* out = (float*)d_out;

    int n = in_sizes[3];
    int E = in_sizes[2] / 2;
    int G = out_size;

    detect_kernel<<<1, 32>>>((const unsigned int*)eidx, E);

    int zeroN = n > G * 64 ? n : G * 64;
    zero_kernel<<<(zeroN + 255) / 256, 256>>>(n, G);

    int initN = n * 16 > E ? n * 16 : E;
    init_kernel<<<(initN + 255) / 256, 256>>>(x, pos, eidx, batch, n, E);

    int B = (n + 255) / 256;
    scan1<<<B, 256>>>(n);
    scan2<<<1, 1024>>>(B, n);
    scan3<<<(n + 255) / 256, 256>>>(n);
    fill_kernel<<<(E + 255) / 256, 256>>>(E);

    // conv1 aggregation: z1 = h0 + gathered neighbor sum (4 lanes/node)
    agg_kernel<4, true><<<(n * 4 + 255) / 256, 256>>>(n);

    // conv1 MLP: z1[n,16] -> h1
    mlp_kernel<16, 1><<<(n + 127) / 128, 128>>>(W1a, b1a, W1b, b1b, 14, n);

    // conv2 aggregation: z2 = h1 + gathered neighbor sum (16 lanes/node)
    agg_kernel<16, false><<<(n * 16 + 255) / 256, 256>>>(n);

    // conv2 MLP: z2[n,64] -> relu -> pooled sums (fused)
    mlp_kernel<64, 2><<<(n + 127) / 128, 128>>>(W2a, b2a, W2b, b2b, 64, n);

    final_kernel<<<(G * 32 + 255) / 256, 256>>>(Wlin, blin, out, G);
}